// round 1
// baseline (speedup 1.0000x reference)
#include <cuda_runtime.h>
#include <cstdint>
#include <cstring>

// Problem constants (shapes fixed by the dataset)
#define HH 32      // neighbors
#define LLL 4      // l channels (1 scalar + 3 vector)
#define CCC 64     // feature channels
#define CMID 8     // hidden
#define COUT 64    // output channels

// ---------------- cp.async helpers ----------------
__device__ __forceinline__ void cpa16(void* dst, const void* src) {
    unsigned d = (unsigned)__cvta_generic_to_shared(dst);
    asm volatile("cp.async.cg.shared.global [%0], [%1], 16;" :: "r"(d), "l"(src));
}
__device__ __forceinline__ void cpa_commit() { asm volatile("cp.async.commit_group;"); }
template<int K> __device__ __forceinline__ void cpa_wait() {
    asm volatile("cp.async.wait_group %0;" :: "n"(K));
}

// Packed f32x2 FMA (Blackwell): acc(2xf32) += a(2xf32) * b(2xf32)
__device__ __forceinline__ void ffma2(unsigned long long& acc,
                                      unsigned long long a, unsigned long long b) {
    asm("fma.rn.f32x2 %0, %1, %2, %0;" : "+l"(acc) : "l"(a), "l"(b));
}

// Issue one 1KB tile (256 floats) stage: 2x 16B per lane
__device__ __forceinline__ void stage_issue(float4* b, const float* src, int lane) {
    cpa16(b + lane,       src + lane * 4);
    cpa16(b + 32 + lane,  src + 128 + lane * 4);
    cpa_commit();
}

__global__ __launch_bounds__(256, 2)
void tp_kernel(const float* __restrict__ s_points,
               const float* __restrict__ nbr_points,
               const float* __restrict__ s_feats,
               const float* __restrict__ nbr_feats,
               const float* __restrict__ W_in,
               const float* __restrict__ W_out,
               const float* __restrict__ w_m0,
               const float* __restrict__ w_m1,
               float* __restrict__ res, int N)
{
    // Per-warp quad-buffered feature tiles (1KB each), depth-2 prefetch
    __shared__ float4 sNF[8][4][64];
    __shared__ float  sVec[8][96];       // vec = nbr_point - s_point, 32 h * 3
    __shared__ float  sWs[CMID * 65];    // W_in second half, padded stride 65 (bank-conflict-free)
    __shared__ float  sWout[COUT * CMID];

    const int tid  = threadIdx.x;
    const int wid  = tid >> 5;
    const int lane = tid & 31;
    const int l    = lane >> 3;   // 0..3 : which l-row this lane computes
    const int m    = lane & 7;    // 0..7 : which mid channel

    // Cooperative load of block-shared weights
    for (int i = tid; i < CMID * CCC; i += 256) {
        int mm = i >> 6, cc = i & 63;
        sWs[mm * 65 + cc] = W_in[mm * 128 + 64 + cc];
    }
    for (int i = tid; i < COUT * CMID; i += 256) sWout[i] = W_out[i];
    __syncthreads();

    const int n = blockIdx.x * 8 + wid;
    if (n >= N) return;   // whole warp exits; no more block syncs below

    // Small mixing weights (broadcast loads)
    const float w00 = __ldg(w_m0 + 0), w01 = __ldg(w_m0 + 1);
    const float w10 = __ldg(w_m0 + 2), w11 = __ldg(w_m0 + 3);
    const float wr  = __ldg(w_m1 + 0), wi = __ldg(w_m1 + 1);

    // W_in neighbor-half row m into registers (packed as f32x2 pairs)
    ulonglong2 wn[16];
    {
        const float4* wrow = reinterpret_cast<const float4*>(W_in + m * 128);
        #pragma unroll
        for (int i = 0; i < 16; i++) {
            float4 t = __ldg(wrow + i);
            memcpy(&wn[i], &t, 16);
        }
    }

    // Stage vec = neighbor_points - s_point into shared (coalesced once per n)
    {
        const float spx = __ldg(s_points + (size_t)n * 3 + 0);
        const float spy = __ldg(s_points + (size_t)n * 3 + 1);
        const float spz = __ldg(s_points + (size_t)n * 3 + 2);
        const float sp3[3] = {spx, spy, spz};
        const float* np = nbr_points + (size_t)n * (HH * 3);
        #pragma unroll
        for (int r = 0; r < 3; r++) {
            int k = lane + 32 * r;
            sVec[wid][k] = __ldg(np + k) - sp3[k % 3];
        }
    }

    float4* buf0 = sNF[wid][0];
    float4* buf1 = sNF[wid][1];
    float4* buf2 = sNF[wid][2];
    float4* buf3 = sNF[wid][3];
    float4* bufs[4] = {buf0, buf1, buf2, buf3};

    const float* sf_src = s_feats   + (size_t)n * (LLL * CCC);
    const float* nf_src = nbr_feats + (size_t)n * HH * (LLL * CCC);

    // stage x: x==0 -> s_feats tile (for msg_s); x>=1 -> neighbor tile h=x-1
    // Prologue: issue stages 0 and 1 (depth-2 pipeline)
    stage_issue(bufs[0], sf_src, lane);
    stage_issue(bufs[1], nf_src, lane);

    float msgs = 0.f;   // msg_s[l][m]  (s-feature contribution, h-invariant)
    float acc  = 0.f;   // out[n][l][m] accumulated over h

    const unsigned FULL = 0xffffffffu;

    for (int x = 0; x <= HH; x++) {
        // Issue stage x+2; buffer (x+2)&3 was consumed at iter x-2 -> safe
        // given the per-iteration __syncwarp below (one-full-iter separation).
        if (x <= HH - 2) {
            stage_issue(bufs[(x + 2) & 3], nf_src + (size_t)(x + 1) * 256, lane);
            cpa_wait<2>();
        } else if (x == HH - 1) {
            cpa_wait<1>();
        } else {
            cpa_wait<0>();
        }
        __syncwarp();

        const float* bp = reinterpret_cast<const float*>(bufs[x & 3]);

        if (x == 0) {
            // msg_s[l][m] = sum_c s_feats[n,l,c] * W_in[m, 64+c]
            float s = 0.f;
            const float* row = bp + l * 64;
            const float* wsr = sWs + m * 65;
            #pragma unroll
            for (int c = 0; c < 64; c++) s = fmaf(row[c], wsr[c], s);
            msgs = s;
        } else {
            const int h = x - 1;

            // ---- Wigner D1 from vec (each lane computes all 9 entries) ----
            float vx = sVec[wid][h * 3 + 0];
            float vy = sVec[wid][h * 3 + 1];
            float vz = sVec[wid][h * 3 + 2];
            float nrm = sqrtf(vx * vx + vy * vy + vz * vz) + 1e-8f;
            float inv = 1.0f / nrm;
            vx *= inv; vy *= inv; vz *= inv;
            float cb = vz;
            float sb = sqrtf(fmaxf(1.0f - cb * cb, 0.0f));
            float rho2 = vx * vx + vy * vy;
            float ca, sa;
            if (rho2 > 1e-24f) { float ir = rsqrtf(rho2); ca = vx * ir; sa = vy * ir; }
            else               { ca = 1.0f; sa = 0.0f; }
            // D = R[perm,:][:,perm], perm=[1,2,0]
            const float D00 = ca,       D02 = -sa;          // D01 = 0
            const float D10 = sb * sa,  D11 = cb,  D12 = sb * ca;
            const float D20 = cb * sa,  D21 = -sb, D22 = cb * ca;

            // ---- msg[l][m] = msg_s + sum_c nf[l][c] * W_in[m][c] ----
            unsigned long long a0 = 0ull, a1 = 0ull;
            const ulonglong2* nfp = reinterpret_cast<const ulonglong2*>(bp) + l * 16;
            #pragma unroll
            for (int i = 0; i < 16; i++) {
                ulonglong2 a = nfp[i];
                ffma2(a0, a.x, wn[i].x);
                ffma2(a1, a.y, wn[i].y);
            }
            float2 p0, p1;
            memcpy(&p0, &a0, 8); memcpy(&p1, &a1, 8);
            float msg = msgs + ((p0.x + p0.y) + (p1.x + p1.y));

            // ---- cross-l mixing via warp shuffles ----
            float msg0 = __shfl_sync(FULL, msg, m);        // l=0 row
            float r1   = __shfl_sync(FULL, msg, 8 + m);    // l=1
            float r2   = __shfl_sync(FULL, msg, 16 + m);   // l=2
            float r3   = __shfl_sync(FULL, msg, 24 + m);   // l=3

            // blk[i] = sum_j D[i][j] * msg[1+j]
            float b0 = fmaf(D00, r1, D02 * r3);            // D01 == 0
            float b1 = fmaf(D10, r1, fmaf(D11, r2, D12 * r3));
            float b2 = fmaf(D20, r1, fmaf(D21, r2, D22 * r3));

            if (l == 0) {
                // out row 0 = o0[0] = w00*msg0 + w01*blk1
                acc += fmaf(w00, msg0, w01 * b1);
            } else {
                float om  = fmaf(wi, b2,  wr * b0);    // wi*xp + wr*xm
                float mid = fmaf(w10, msg0, w11 * b1); // o0[1]
                float op  = fmaf(wr, b2, -wi * b0);    // wr*xp - wi*xm
                // back[l-1] = sum_j D[j][l-1] * blk_o[j]  (column l-1 of D)
                float Da = (l == 1) ? D00 : ((l == 2) ? 0.f : D02);
                float Db = (l == 1) ? D10 : ((l == 2) ? D11 : D12);
                float Dc = (l == 1) ? D20 : ((l == 2) ? D21 : D22);
                acc += fmaf(om, Da, fmaf(mid, Db, op * Dc));
            }
        }
    }

    // ---- epilogue: res[n,l,o] = sum_m out[l][m] * W_out[o][m] ----
    float vals[8];
    #pragma unroll
    for (int mm = 0; mm < 8; mm++) vals[mm] = __shfl_sync(FULL, acc, l * 8 + mm);

    float outv[8];
    #pragma unroll
    for (int k = 0; k < 8; k++) {
        const float* wo = sWout + (m * 8 + k) * 8;   // W_out row o = m*8+k
        float s = 0.f;
        #pragma unroll
        for (int mm = 0; mm < 8; mm++) s = fmaf(vals[mm], wo[mm], s);
        outv[k] = s;
    }
    float4* dst = reinterpret_cast<float4*>(res + (size_t)n * (LLL * COUT) + l * COUT + m * 8);
    dst[0] = make_float4(outv[0], outv[1], outv[2], outv[3]);
    dst[1] = make_float4(outv[4], outv[5], outv[6], outv[7]);
}

extern "C" void kernel_launch(void* const* d_in, const int* in_sizes, int n_in,
                              void* d_out, int out_size)
{
    const float* s_points   = (const float*)d_in[0];
    const float* nbr_points = (const float*)d_in[1];
    const float* s_feats    = (const float*)d_in[2];
    const float* nbr_feats  = (const float*)d_in[3];
    // d_in[4] = values (N,H) — unused by the reference computation
    const float* W_in       = (const float*)d_in[5];
    const float* W_out      = (const float*)d_in[6];
    const float* w_m0       = (const float*)d_in[7];
    const float* w_m1       = (const float*)d_in[8];

    const int N = in_sizes[3] / (HH * LLL * CCC);   // neighbor_feats element count
    const int blocks = (N + 7) / 8;                 // warp per n, 8 warps per block

    tp_kernel<<<blocks, 256>>>(s_points, nbr_points, s_feats, nbr_feats,
                               W_in, W_out, w_m0, w_m1, (float*)d_out, N);
}

// round 2
// speedup vs baseline: 1.1314x; 1.1314x over previous
#include <cuda_runtime.h>
#include <cstdint>
#include <cstring>

// Problem constants (shapes fixed by the dataset)
#define HH 32      // neighbors
#define LLL 4      // l channels (1 scalar + 3 vector)
#define CCC 64     // feature channels
#define CMID 8     // hidden
#define COUT 64    // output channels

// Padded tile row stride: 68 floats = 17 float4. Bank of float4 j in row l:
// (68l + 4j) mod 32 = (4l + 4j) mod 32 -> distinct across l  => conflict-free.
#define SROW4 17

// ---------------- cp.async helpers ----------------
__device__ __forceinline__ void cpa16(void* dst, const void* src) {
    unsigned d = (unsigned)__cvta_generic_to_shared(dst);
    asm volatile("cp.async.cg.shared.global [%0], [%1], 16;" :: "r"(d), "l"(src));
}
__device__ __forceinline__ void cpa_commit() { asm volatile("cp.async.commit_group;"); }
template<int K> __device__ __forceinline__ void cpa_wait() {
    asm volatile("cp.async.wait_group %0;" :: "n"(K));
}

// Packed f32x2 FMA (Blackwell): acc(2xf32) += a(2xf32) * b(2xf32)
__device__ __forceinline__ void ffma2(unsigned long long& acc,
                                      unsigned long long a, unsigned long long b) {
    asm("fma.rn.f32x2 %0, %1, %2, %0;" : "+l"(acc) : "l"(a), "l"(b));
}

// Issue one 1KB tile (256 floats) into a PADDED 4x68-float shared tile.
// chunk k (16B) of source row r=k/16, col c=k%16 -> shared float4 index r*17+c.
__device__ __forceinline__ void stage_issue(float4* b, const float* src, int lane) {
    const int r0 = lane >> 4, c0 = lane & 15;
    cpa16(b + r0 * SROW4 + c0,       src + lane * 4);
    cpa16(b + (r0 + 2) * SROW4 + c0, src + (lane + 32) * 4);
    cpa_commit();
}

__global__ __launch_bounds__(256, 2)
void tp_kernel(const float* __restrict__ s_points,
               const float* __restrict__ nbr_points,
               const float* __restrict__ s_feats,
               const float* __restrict__ nbr_feats,
               const float* __restrict__ W_in,
               const float* __restrict__ W_out,
               const float* __restrict__ w_m0,
               const float* __restrict__ w_m1,
               float* __restrict__ res, int N)
{
    // Per-warp quad-buffered padded feature tiles (4*68 floats = 1088B each)
    __shared__ float4 sNF[8][4][4 * SROW4];
    __shared__ float  sVec[8][96];          // vec = nbr_point - s_point, 32 h * 3
    __shared__ float4 sWs4[CMID * SROW4];   // W_in second half, padded (conflict-free)
    __shared__ float4 sWoutT4[CMID * 18];   // W_out TRANSPOSED [mm][o], stride 72 floats

    const int tid  = threadIdx.x;
    const int wid  = tid >> 5;
    const int lane = tid & 31;
    const int l    = lane >> 3;   // 0..3 : which l-row this lane computes
    const int m    = lane & 7;    // 0..7 : which mid channel

    // Cooperative load of block-shared weights
    {
        float* ws = reinterpret_cast<float*>(sWs4);
        for (int i = tid; i < CMID * CCC; i += 256) {
            int mm = i >> 6, cc = i & 63;
            ws[mm * 68 + cc] = W_in[mm * 128 + 64 + cc];
        }
        float* wt = reinterpret_cast<float*>(sWoutT4);
        for (int i = tid; i < COUT * CMID; i += 256) {
            int o = i >> 3, mm = i & 7;
            wt[mm * 72 + o] = W_out[i];
        }
    }
    __syncthreads();

    const int n = blockIdx.x * 8 + wid;
    if (n >= N) return;   // whole warp exits; no more block syncs below

    // Small mixing weights (broadcast loads)
    const float w00 = __ldg(w_m0 + 0), w01 = __ldg(w_m0 + 1);
    const float w10 = __ldg(w_m0 + 2), w11 = __ldg(w_m0 + 3);
    const float wr  = __ldg(w_m1 + 0), wi = __ldg(w_m1 + 1);

    // W_in neighbor-half row m into registers (packed as f32x2 pairs)
    ulonglong2 wn[16];
    {
        const float4* wrow = reinterpret_cast<const float4*>(W_in + m * 128);
        #pragma unroll
        for (int i = 0; i < 16; i++) {
            float4 t = __ldg(wrow + i);
            memcpy(&wn[i], &t, 16);
        }
    }

    // Stage vec = neighbor_points - s_point into shared (coalesced once per n)
    {
        const float spx = __ldg(s_points + (size_t)n * 3 + 0);
        const float spy = __ldg(s_points + (size_t)n * 3 + 1);
        const float spz = __ldg(s_points + (size_t)n * 3 + 2);
        const float sp3[3] = {spx, spy, spz};
        const float* np = nbr_points + (size_t)n * (HH * 3);
        #pragma unroll
        for (int r = 0; r < 3; r++) {
            int k = lane + 32 * r;
            sVec[wid][k] = __ldg(np + k) - sp3[k % 3];
        }
    }

    float4* bufs[4] = {sNF[wid][0], sNF[wid][1], sNF[wid][2], sNF[wid][3]};

    const float* sf_src = s_feats   + (size_t)n * (LLL * CCC);
    const float* nf_src = nbr_feats + (size_t)n * HH * (LLL * CCC);

    // stage x: x==0 -> s_feats tile (for msg_s); x>=1 -> neighbor tile h=x-1
    // Prologue: depth-3 pipeline, issue stages 0,1,2
    stage_issue(bufs[0], sf_src, lane);
    stage_issue(bufs[1], nf_src, lane);
    stage_issue(bufs[2], nf_src + 256, lane);

    float msgs = 0.f;   // msg_s[l][m]  (s-feature contribution, h-invariant)
    float acc  = 0.f;   // out[n][l][m] accumulated over h

    const unsigned FULL = 0xffffffffu;

    for (int x = 0; x <= HH; x++) {
        if (x <= HH - 3) {
            stage_issue(bufs[(x + 3) & 3], nf_src + (size_t)(x + 2) * 256, lane);
            cpa_wait<3>();
        } else if (x == HH - 2) {
            cpa_wait<2>();
        } else if (x == HH - 1) {
            cpa_wait<1>();
        } else {
            cpa_wait<0>();
        }
        __syncwarp();

        const ulonglong2* tile = reinterpret_cast<const ulonglong2*>(bufs[x & 3]);
        const ulonglong2* nfp  = tile + l * SROW4;   // padded row -> conflict-free

        if (x == 0) {
            // msg_s[l][m] = sum_c s_feats[n,l,c] * W_in[m, 64+c]  (packed FMA)
            const ulonglong2* wsr = reinterpret_cast<const ulonglong2*>(sWs4) + m * SROW4;
            unsigned long long a0 = 0ull, a1 = 0ull;
            #pragma unroll
            for (int i = 0; i < 16; i++) {
                ulonglong2 a = nfp[i], w = wsr[i];
                ffma2(a0, a.x, w.x);
                ffma2(a1, a.y, w.y);
            }
            float2 p0, p1;
            memcpy(&p0, &a0, 8); memcpy(&p1, &a1, 8);
            msgs = (p0.x + p0.y) + (p1.x + p1.y);
        } else {
            const int h = x - 1;

            // ---- Wigner D1 from vec (each lane computes all 9 entries) ----
            float vx = sVec[wid][h * 3 + 0];
            float vy = sVec[wid][h * 3 + 1];
            float vz = sVec[wid][h * 3 + 2];
            float nrm = sqrtf(vx * vx + vy * vy + vz * vz) + 1e-8f;
            float inv = 1.0f / nrm;
            vx *= inv; vy *= inv; vz *= inv;
            float cb = vz;
            float sb = sqrtf(fmaxf(1.0f - cb * cb, 0.0f));
            float rho2 = vx * vx + vy * vy;
            float ca, sa;
            if (rho2 > 1e-24f) { float ir = rsqrtf(rho2); ca = vx * ir; sa = vy * ir; }
            else               { ca = 1.0f; sa = 0.0f; }
            // D = R[perm,:][:,perm], perm=[1,2,0]
            const float D00 = ca,       D02 = -sa;          // D01 = 0
            const float D10 = sb * sa,  D11 = cb,  D12 = sb * ca;
            const float D20 = cb * sa,  D21 = -sb, D22 = cb * ca;

            // ---- msg[l][m] = msg_s + sum_c nf[l][c] * W_in[m][c] ----
            unsigned long long a0 = 0ull, a1 = 0ull;
            #pragma unroll
            for (int i = 0; i < 16; i++) {
                ulonglong2 a = nfp[i];
                ffma2(a0, a.x, wn[i].x);
                ffma2(a1, a.y, wn[i].y);
            }
            float2 p0, p1;
            memcpy(&p0, &a0, 8); memcpy(&p1, &a1, 8);
            float msg = msgs + ((p0.x + p0.y) + (p1.x + p1.y));

            // ---- cross-l mixing via warp shuffles ----
            float msg0 = __shfl_sync(FULL, msg, m);        // l=0 row
            float r1   = __shfl_sync(FULL, msg, 8 + m);    // l=1
            float r2   = __shfl_sync(FULL, msg, 16 + m);   // l=2
            float r3   = __shfl_sync(FULL, msg, 24 + m);   // l=3

            // blk[i] = sum_j D[i][j] * msg[1+j]
            float b0 = fmaf(D00, r1, D02 * r3);            // D01 == 0
            float b1 = fmaf(D10, r1, fmaf(D11, r2, D12 * r3));
            float b2 = fmaf(D20, r1, fmaf(D21, r2, D22 * r3));

            if (l == 0) {
                // out row 0 = o0[0] = w00*msg0 + w01*blk1
                acc += fmaf(w00, msg0, w01 * b1);
            } else {
                float om  = fmaf(wi, b2,  wr * b0);    // wi*xp + wr*xm
                float mid = fmaf(w10, msg0, w11 * b1); // o0[1]
                float op  = fmaf(wr, b2, -wi * b0);    // wr*xp - wi*xm
                // back[l-1] = sum_j D[j][l-1] * blk_o[j]  (column l-1 of D)
                float Da = (l == 1) ? D00 : ((l == 2) ? 0.f : D02);
                float Db = (l == 1) ? D10 : ((l == 2) ? D11 : D12);
                float Dc = (l == 1) ? D20 : ((l == 2) ? D21 : D22);
                acc += fmaf(om, Da, fmaf(mid, Db, op * Dc));
            }
        }
    }

    // ---- epilogue: res[n,l,o] = sum_m out[l][m] * W_out[o][m] ----
    // sWoutT is [mm][o] with 72-float row stride: float4 bank group
    // (8mm + 8m + 4j) mod 32 -> only m vs m+4 collide (2-way worst case).
    float vals[8];
    #pragma unroll
    for (int mm = 0; mm < 8; mm++) vals[mm] = __shfl_sync(FULL, acc, l * 8 + mm);

    float4 o0 = make_float4(0.f, 0.f, 0.f, 0.f);
    float4 o1 = make_float4(0.f, 0.f, 0.f, 0.f);
    const float* wtf = reinterpret_cast<const float*>(sWoutT4);
    #pragma unroll
    for (int mm = 0; mm < 8; mm++) {
        const float4* wo = reinterpret_cast<const float4*>(wtf + mm * 72 + m * 8);
        float4 w0 = wo[0], w1 = wo[1];
        float v = vals[mm];
        o0.x = fmaf(v, w0.x, o0.x); o0.y = fmaf(v, w0.y, o0.y);
        o0.z = fmaf(v, w0.z, o0.z); o0.w = fmaf(v, w0.w, o0.w);
        o1.x = fmaf(v, w1.x, o1.x); o1.y = fmaf(v, w1.y, o1.y);
        o1.z = fmaf(v, w1.z, o1.z); o1.w = fmaf(v, w1.w, o1.w);
    }
    float4* dst = reinterpret_cast<float4*>(res + (size_t)n * (LLL * COUT) + l * COUT + m * 8);
    dst[0] = o0;
    dst[1] = o1;
}

extern "C" void kernel_launch(void* const* d_in, const int* in_sizes, int n_in,
                              void* d_out, int out_size)
{
    const float* s_points   = (const float*)d_in[0];
    const float* nbr_points = (const float*)d_in[1];
    const float* s_feats    = (const float*)d_in[2];
    const float* nbr_feats  = (const float*)d_in[3];
    // d_in[4] = values (N,H) — unused by the reference computation
    const float* W_in       = (const float*)d_in[5];
    const float* W_out      = (const float*)d_in[6];
    const float* w_m0       = (const float*)d_in[7];
    const float* w_m1       = (const float*)d_in[8];

    const int N = in_sizes[3] / (HH * LLL * CCC);   // neighbor_feats element count
    const int blocks = (N + 7) / 8;                 // warp per n, 8 warps per block

    tp_kernel<<<blocks, 256>>>(s_points, nbr_points, s_feats, nbr_feats,
                               W_in, W_out, w_m0, w_m1, (float*)d_out, N);
}

// round 5
// speedup vs baseline: 1.5877x; 1.4033x over previous
#include <cuda_runtime.h>
#include <cstdint>
#include <cstring>

// Problem constants (shapes fixed by the dataset)
#define HH 32      // neighbors (== warp size, exploited for Wigner precompute)
#define LLL 4      // l channels
#define CCC 64     // feature channels
#define CMID 8     // hidden
#define COUT 64    // output channels

// ---------------- cp.async helpers ----------------
__device__ __forceinline__ void cpa16(void* dst, const void* src) {
    unsigned d = (unsigned)__cvta_generic_to_shared(dst);
    asm volatile("cp.async.cg.shared.global [%0], [%1], 16;" :: "r"(d), "l"(src));
}
__device__ __forceinline__ void cpa_commit() { asm volatile("cp.async.commit_group;"); }
template<int K> __device__ __forceinline__ void cpa_wait() {
    asm volatile("cp.async.wait_group %0;" :: "n"(K));
}

// Packed f32x2 FMA (Blackwell): acc(2xf32) += a(2xf32) * b(2xf32)
__device__ __forceinline__ void ffma2(unsigned long long& acc,
                                      unsigned long long a, unsigned long long b) {
    asm("fma.rn.f32x2 %0, %1, %2, %0;" : "+l"(acc) : "l"(a), "l"(b));
}
__device__ __forceinline__ float2 unpack2(unsigned long long v) {
    float2 f; memcpy(&f, &v, 8); return f;
}
__device__ __forceinline__ ulonglong2 pack4(float4 v) {
    ulonglong2 u; memcpy(&u, &v, 16); return u;
}

// Stage one 1KB tile. Source chunk k (16B) -> smem slot (k>>1) + ((k&1)<<5).
// Consumer: lane i reads slots i and i+32 = floats [8i, 8i+8)  (conflict-free).
__device__ __forceinline__ void stage_issue(float4* b, const float* src, int lane) {
    const int k2 = lane + 32;
    cpa16(b + ((lane >> 1) + ((lane & 1) << 5)), src + lane * 4);
    cpa16(b + ((k2 >> 1) + ((k2 & 1) << 5)),     src + k2 * 4);
    cpa_commit();
}

// 3-round keep/send butterfly over 8-lane groups: lane (g*8+q) ends with
// sum over its group of v[q].
__device__ __forceinline__ float reduce8(const float* v, int q) {
    const unsigned FULL = 0xffffffffu;
    bool s4 = (q & 4) != 0;
    float a0 = (s4 ? v[4] : v[0]) + __shfl_xor_sync(FULL, s4 ? v[0] : v[4], 4);
    float a1 = (s4 ? v[5] : v[1]) + __shfl_xor_sync(FULL, s4 ? v[1] : v[5], 4);
    float a2 = (s4 ? v[6] : v[2]) + __shfl_xor_sync(FULL, s4 ? v[2] : v[6], 4);
    float a3 = (s4 ? v[7] : v[3]) + __shfl_xor_sync(FULL, s4 ? v[3] : v[7], 4);
    bool s2 = (q & 2) != 0;
    float b0c = (s2 ? a2 : a0) + __shfl_xor_sync(FULL, s2 ? a0 : a2, 2);
    float b1c = (s2 ? a3 : a1) + __shfl_xor_sync(FULL, s2 ? a1 : a3, 2);
    bool s1 = (q & 1) != 0;
    return (s1 ? b1c : b0c) + __shfl_xor_sync(FULL, s1 ? b0c : b1c, 1);
}

// Per-lane 8x8 GEMM panel: partials for all 8 m rows over this lane's 8 floats.
__device__ __forceinline__ void gemm8(const unsigned long long* wb,
                                      ulonglong2 u0, ulonglong2 u1, float* vals) {
    #pragma unroll
    for (int m2 = 0; m2 < 8; m2++) {
        unsigned long long am = 0ull;
        ffma2(am, u0.x, wb[m2 * 4 + 0]);
        ffma2(am, u0.y, wb[m2 * 4 + 1]);
        ffma2(am, u1.x, wb[m2 * 4 + 2]);
        ffma2(am, u1.y, wb[m2 * 4 + 3]);
        float2 f = unpack2(am);
        vals[m2] = f.x + f.y;
    }
}

__global__ __launch_bounds__(256, 2)
void tp_kernel(const float* __restrict__ s_points,
               const float* __restrict__ nbr_points,
               const float* __restrict__ s_feats,
               const float* __restrict__ nbr_feats,
               const float* __restrict__ W_in,
               const float* __restrict__ W_out,
               const float* __restrict__ w_m0,
               const float* __restrict__ w_m1,
               float* __restrict__ res, int N)
{
    __shared__ float4 sNF[8][4 * 64];     // per-warp quad-buffered 1KB tiles
    __shared__ float4 sWoutT[CMID * 16];  // W_out^T, even/odd split per row

    const int tid  = threadIdx.x;
    const int wid  = tid >> 5;
    const int lane = tid & 31;
    const int l    = lane >> 3;   // 0..3
    const int q    = lane & 7;    // 0..7
    const unsigned FULL = 0xffffffffu;

    // Stage W_out transposed + split-swizzled: value W_out[o][mm] -> row mm,
    // float4 f=o>>2 stored at slot (f>>1)+((f&1)<<3), float pos o&3.
    {
        float* wt = reinterpret_cast<float*>(sWoutT);
        for (int i = tid; i < COUT * CMID; i += 256) {
            int o = i >> 3, mm = i & 7;
            int f = o >> 2;
            int slot = (f >> 1) + ((f & 1) << 3);
            wt[mm * 64 + slot * 4 + (o & 3)] = W_out[i];
        }
    }
    __syncthreads();

    const int n = blockIdx.x * 8 + wid;
    if (n >= N) return;   // whole warp; no block syncs below

    const float w00 = __ldg(w_m0 + 0), w01 = __ldg(w_m0 + 1);
    const float w10 = __ldg(w_m0 + 2), w11 = __ldg(w_m0 + 3);
    const float wr  = __ldg(w_m1 + 0), wi = __ldg(w_m1 + 1);

    // ---- Wigner D1 precompute: lane h computes D for neighbor h (H==32) ----
    float D00, D02, D10, D11, D12, D20, D21, D22;
    {
        const float* np = nbr_points + (size_t)n * 96 + lane * 3;
        float vx = __ldg(np + 0) - __ldg(s_points + n * 3 + 0);
        float vy = __ldg(np + 1) - __ldg(s_points + n * 3 + 1);
        float vz = __ldg(np + 2) - __ldg(s_points + n * 3 + 2);
        float nrm = sqrtf(vx * vx + vy * vy + vz * vz) + 1e-8f;
        float inv = 1.0f / nrm;
        vx *= inv; vy *= inv; vz *= inv;
        float cb = vz;
        float sb = sqrtf(fmaxf(1.0f - cb * cb, 0.0f));
        float rho2 = vx * vx + vy * vy;
        float ca, sa;
        if (rho2 > 1e-24f) { float ir = rsqrtf(rho2); ca = vx * ir; sa = vy * ir; }
        else               { ca = 1.0f; sa = 0.0f; }
        D00 = ca;      D02 = -sa;                       // D01 = 0
        D10 = sb * sa; D11 = cb;  D12 = sb * ca;
        D20 = cb * sa; D21 = -sb; D22 = cb * ca;
    }

    // ---- start cp.async pipeline (depth 3) ----
    float4* buf = sNF[wid];
    const float* nf_src = nbr_feats + (size_t)n * (HH * LLL * CCC);
    stage_issue(buf,       nf_src,       lane);
    stage_issue(buf + 64,  nf_src + 256, lane);
    stage_issue(buf + 128, nf_src + 512, lane);

    // 8x8 weight block per lane (cols q*8..q*8+8 for all 8 m rows), packed.
    unsigned long long wb[32];

    // ---- msg_s once (s-feature half of W_in), overlapped with async flight ----
    float msgs;
    {
        const float* base = W_in + 64 + q * 8;
        #pragma unroll
        for (int m2 = 0; m2 < 8; m2++) {
            const float4* p = reinterpret_cast<const float4*>(base + m2 * 128);
            ulonglong2 ua = pack4(__ldg(p));
            ulonglong2 ub = pack4(__ldg(p + 1));
            wb[m2 * 4 + 0] = ua.x; wb[m2 * 4 + 1] = ua.y;
            wb[m2 * 4 + 2] = ub.x; wb[m2 * 4 + 3] = ub.y;
        }
        const float4* sfp = reinterpret_cast<const float4*>(
            s_feats + (size_t)n * 256 + l * 64 + q * 8);
        ulonglong2 t0 = pack4(__ldg(sfp));
        ulonglong2 t1 = pack4(__ldg(sfp + 1));
        float vals[8];
        gemm8(wb, t0, t1, vals);
        msgs = reduce8(vals, q);
    }
    // Neighbor-half weights, loop-invariant in regs
    {
        const float* base = W_in + q * 8;
        #pragma unroll
        for (int m2 = 0; m2 < 8; m2++) {
            const float4* p = reinterpret_cast<const float4*>(base + m2 * 128);
            ulonglong2 ua = pack4(__ldg(p));
            ulonglong2 ub = pack4(__ldg(p + 1));
            wb[m2 * 4 + 0] = ua.x; wb[m2 * 4 + 1] = ua.y;
            wb[m2 * 4 + 2] = ub.x; wb[m2 * 4 + 3] = ub.y;
        }
    }

    float acc = 0.f;

    // Main loop: wait, sync, compute, then issue h+3 (sync separates the
    // last read of the buffer from its overwrite -> no WAR window).
    for (int h = 0; h < HH; h++) {
        if (h < HH - 3)      { cpa_wait<2>(); }
        else if (h == HH - 3){ cpa_wait<2>(); }
        else if (h == HH - 2){ cpa_wait<1>(); }
        else                 { cpa_wait<0>(); }
        __syncwarp();

        const float4* bp = buf + (h & 3) * 64;
        ulonglong2 u0 = pack4(bp[lane]);        // floats [8*lane .. 8*lane+8)
        ulonglong2 u1 = pack4(bp[lane + 32]);
        float vals[8];
        gemm8(wb, u0, u1, vals);
        float msg = reduce8(vals, q) + msgs;    // lane l*8+q holds msg[l][q]

        // broadcast this h's Wigner entries from lane h
        float d00 = __shfl_sync(FULL, D00, h);
        float d02 = __shfl_sync(FULL, D02, h);
        float d10 = __shfl_sync(FULL, D10, h);
        float d11 = __shfl_sync(FULL, D11, h);
        float d12 = __shfl_sync(FULL, D12, h);
        float d20 = __shfl_sync(FULL, D20, h);
        float d21 = __shfl_sync(FULL, D21, h);
        float d22 = __shfl_sync(FULL, D22, h);

        float msg0 = __shfl_sync(FULL, msg, q);
        float r1   = __shfl_sync(FULL, msg, 8 + q);
        float r2   = __shfl_sync(FULL, msg, 16 + q);
        float r3   = __shfl_sync(FULL, msg, 24 + q);

        float b0 = fmaf(d00, r1, d02 * r3);     // d01 == 0
        float b1 = fmaf(d10, r1, fmaf(d11, r2, d12 * r3));
        float b2 = fmaf(d20, r1, fmaf(d21, r2, d22 * r3));

        if (l == 0) {
            acc += fmaf(w00, msg0, w01 * b1);
        } else {
            float om  = fmaf(wi, b2,  wr * b0);
            float mid = fmaf(w10, msg0, w11 * b1);
            float op  = fmaf(wr, b2, -wi * b0);
            float Da = (l == 1) ? d00 : ((l == 2) ? 0.f : d02);
            float Db = (l == 1) ? d10 : ((l == 2) ? d11 : d12);
            float Dc = (l == 1) ? d20 : ((l == 2) ? d21 : d22);
            acc += fmaf(om, Da, fmaf(mid, Db, op * Dc));
        }

        // Prefetch tile h+3 into the buffer freed at iteration h-1
        if (h < HH - 3) {
            stage_issue(buf + ((h + 3) & 3) * 64, nf_src + (size_t)(h + 3) * 256, lane);
        }
    }

    // ---- epilogue: res[n,l,o] = sum_mm acc[l][mm] * W_out[o][mm] ----
    float vals8[8];
    #pragma unroll
    for (int mm = 0; mm < 8; mm++) vals8[mm] = __shfl_sync(FULL, acc, l * 8 + mm);

    float4 o0 = make_float4(0.f, 0.f, 0.f, 0.f);
    float4 o1 = make_float4(0.f, 0.f, 0.f, 0.f);
    #pragma unroll
    for (int mm = 0; mm < 8; mm++) {
        float4 wv0 = sWoutT[mm * 16 + q];       // o = q*8..q*8+4
        float4 wv1 = sWoutT[mm * 16 + q + 8];   // o = q*8+4..q*8+8
        float v = vals8[mm];
        o0.x = fmaf(v, wv0.x, o0.x); o0.y = fmaf(v, wv0.y, o0.y);
        o0.z = fmaf(v, wv0.z, o0.z); o0.w = fmaf(v, wv0.w, o0.w);
        o1.x = fmaf(v, wv1.x, o1.x); o1.y = fmaf(v, wv1.y, o1.y);
        o1.z = fmaf(v, wv1.z, o1.z); o1.w = fmaf(v, wv1.w, o1.w);
    }
    float4* dst = reinterpret_cast<float4*>(res + (size_t)n * 256 + l * 64 + q * 8);
    dst[0] = o0;
    dst[1] = o1;
}

extern "C" void kernel_launch(void* const* d_in, const int* in_sizes, int n_in,
                              void* d_out, int out_size)
{
    const float* s_points   = (const float*)d_in[0];
    const float* nbr_points = (const float*)d_in[1];
    const float* s_feats    = (const float*)d_in[2];
    const float* nbr_feats  = (const float*)d_in[3];
    // d_in[4] = values (N,H) — unused by the reference computation
    const float* W_in       = (const float*)d_in[5];
    const float* W_out      = (const float*)d_in[6];
    const float* w_m0       = (const float*)d_in[7];
    const float* w_m1       = (const float*)d_in[8];

    const int N = in_sizes[3] / (HH * LLL * CCC);
    const int blocks = (N + 7) / 8;   // warp per n, 8 warps per block

    tp_kernel<<<blocks, 256>>>(s_points, nbr_points, s_feats, nbr_feats,
                               W_in, W_out, w_m0, w_m1, (float*)d_out, N);
}